// round 12
// baseline (speedup 1.0000x reference)
#include <cuda_runtime.h>
#include <cuda_bf16.h>
#include <cstdint>

#define NN 6144
#define IN_DIM 512
#define CHANNELS 4
#define C_DIM 64
#define FDIM 256          // CHANNELS * C_DIM
#define CAP 128           // max neighbors per row (mean ~31, sd ~5.5)

// -------- scratch (device globals; no allocation allowed) --------
// Rows of g_feats are stored PERMUTED: canonical element e (owner lane
// l = e>>3, sub s = e&7) lives at float offset (s>=4)*128 + l*4 + (s&3).
// Dense per-lane 16B neighbor loads + 8-lane channel groups (5-shfl softmax).
// Row NN is a permanent all-zero row (sentinel target).
__device__ float g_featsA[(size_t)(NN + 1) * FDIM];
__device__ float g_featsB[(size_t)(NN + 1) * FDIM];
__device__ int   g_ell[(size_t)NN * CAP + 64];
__device__ int   g_deg[NN];

#define FMA2(d, a, b, c) \
    asm("fma.rn.f32x2 %0, %1, %2, %3;" : "=l"(d) : "l"(a), "l"(b), "l"(c))
#define UNPACK2(lo, hi, s) \
    asm("mov.b64 {%0, %1}, %2;" : "=f"(lo), "=f"(hi) : "l"(s))

// ============================================================
// Kernel 1: dense adj -> ELL (order-preserving, deterministic)
// warp/row, int4 + 4-ballot compaction, sentinel padding to x4.
// ============================================================
__global__ __launch_bounds__(256) void build_ell_kernel(const int* __restrict__ adj) {
    int row = blockIdx.x * 8 + (threadIdx.x >> 5);
    int lane = threadIdx.x & 31;
    const int4* arow = (const int4*)(adj + (size_t)row * NN);
    unsigned lt = (1u << lane) - 1u;
    int total = 0;
    int* erow = g_ell + (size_t)row * CAP;
    for (int it = 0; it < NN / 128; it++) {
        int4 v = arow[it * 32 + lane];
        bool p0 = v.x > 0, p1 = v.y > 0, p2 = v.z > 0, p3 = v.w > 0;
        unsigned b0 = __ballot_sync(0xffffffffu, p0);
        unsigned b1 = __ballot_sync(0xffffffffu, p1);
        unsigned b2 = __ballot_sync(0xffffffffu, p2);
        unsigned b3 = __ballot_sync(0xffffffffu, p3);
        int basec = __popc(b0 & lt) + __popc(b1 & lt) + __popc(b2 & lt) + __popc(b3 & lt);
        int idx0 = it * 128 + lane * 4;
        int pos = total + basec;
        if (p0) { if (pos < CAP) erow[pos] = idx0; pos++; }
        if (p1) { if (pos < CAP) erow[pos] = idx0 + 1; pos++; }
        if (p2) { if (pos < CAP) erow[pos] = idx0 + 2; pos++; }
        if (p3) { if (pos < CAP) erow[pos] = idx0 + 3; }
        total += __popc(b0) + __popc(b1) + __popc(b2) + __popc(b3);
    }
    int tc = total < CAP ? total : CAP;
    int pad = (tc + 3) & ~3;
    if (lane < pad - tc) erow[tc + lane] = NN;   // sentinel -> zero row
    if (lane == 0) g_deg[row] = pad;
}

// ============================================================
// Kernel 2: feats0 = l2norm(features @ W + b) -> permuted layout.
// 64x64 tile, 256 threads, 4x4 microtile, BK=16, packed f32x2 FMA.
// B is pre-DUPLICATED into smem pairs at tile-load time, so the
// inner step is 2 LDS.64 + 2 LDS.128 + 8 FMA2 (no PACK movs).
// ============================================================
__global__ __launch_bounds__(256) void project_kernel(const float* __restrict__ feat,
                                                      const float* __restrict__ W,
                                                      const float* __restrict__ bias) {
    __shared__ float sA[16][64];      // [d][row]
    __shared__ float sB2[16][128];    // [d][col j duplicated -> (w,w) at 2j]
    __shared__ float s_scale[64];

    const int c  = blockIdx.y;
    const int n0 = blockIdx.x * 64;
    const int t  = threadIdx.x;
    const int tx = t & 15, ty = t >> 4;

    unsigned long long acc2[2][4];
#pragma unroll
    for (int i = 0; i < 2; i++)
#pragma unroll
        for (int j = 0; j < 4; j++) acc2[i][j] = 0ull;

    const float* Wc = W + (size_t)c * IN_DIM * C_DIM;
    const int lrow = t >> 2, lseg = t & 3;
    const int ld   = t >> 4, lks  = t & 15;

    for (int d0 = 0; d0 < IN_DIM; d0 += 16) {
        float4 a = *(const float4*)(feat + (size_t)(n0 + lrow) * IN_DIM + d0 + lseg * 4);
        sA[lseg * 4 + 0][lrow] = a.x;
        sA[lseg * 4 + 1][lrow] = a.y;
        sA[lseg * 4 + 2][lrow] = a.z;
        sA[lseg * 4 + 3][lrow] = a.w;
        float4 bv = *(const float4*)(Wc + (size_t)(d0 + ld) * C_DIM + lks * 4);
        float4* bdst = (float4*)&sB2[ld][lks * 8];
        bdst[0] = make_float4(bv.x, bv.x, bv.y, bv.y);
        bdst[1] = make_float4(bv.z, bv.z, bv.w, bv.w);
        __syncthreads();
#pragma unroll
        for (int d = 0; d < 16; d++) {
            unsigned long long ap0 = *(const unsigned long long*)&sA[d][ty * 4];
            unsigned long long ap1 = *(const unsigned long long*)&sA[d][ty * 4 + 2];
            const float4* bsrc = (const float4*)&sB2[d][tx * 8];
            float4 bq0 = bsrc[0], bq1 = bsrc[1];
            unsigned long long bp0 = *(unsigned long long*)&bq0.x;
            unsigned long long bp1 = *(unsigned long long*)&bq0.z;
            unsigned long long bp2 = *(unsigned long long*)&bq1.x;
            unsigned long long bp3 = *(unsigned long long*)&bq1.z;
            FMA2(acc2[0][0], ap0, bp0, acc2[0][0]);
            FMA2(acc2[0][1], ap0, bp1, acc2[0][1]);
            FMA2(acc2[0][2], ap0, bp2, acc2[0][2]);
            FMA2(acc2[0][3], ap0, bp3, acc2[0][3]);
            FMA2(acc2[1][0], ap1, bp0, acc2[1][0]);
            FMA2(acc2[1][1], ap1, bp1, acc2[1][1]);
            FMA2(acc2[1][2], ap1, bp2, acc2[1][2]);
            FMA2(acc2[1][3], ap1, bp3, acc2[1][3]);
        }
        __syncthreads();
    }

    float r[4][4];
#pragma unroll
    for (int i = 0; i < 2; i++)
#pragma unroll
        for (int j = 0; j < 4; j++)
            UNPACK2(r[2 * i][j], r[2 * i + 1][j], acc2[i][j]);

    float4 bb4 = *(const float4*)(bias + c * C_DIM + tx * 4);
    float bb[4] = {bb4.x, bb4.y, bb4.z, bb4.w};
    float ss[4];
#pragma unroll
    for (int i = 0; i < 4; i++) {
        float s = 0.f;
#pragma unroll
        for (int j = 0; j < 4; j++) {
            r[i][j] += bb[j];
            s += r[i][j] * r[i][j];
        }
        ss[i] = s;
    }
#pragma unroll
    for (int off = 1; off < 16; off <<= 1)
#pragma unroll
        for (int i = 0; i < 4; i++) ss[i] += __shfl_xor_sync(0xffffffffu, ss[i], off);
    if (tx == 0) {
#pragma unroll
        for (int i = 0; i < 4; i++) s_scale[ty * 4 + i] = rsqrtf(fmaxf(ss[i], 1e-24f));
    }
    __syncthreads();
    // permuted store position for canonical cols c*64 + tx*4 .. +4:
    // owner lane l = c*8 + (tx>>1), half = tx&1
    const int ppos = (tx & 1) * 128 + (c * 8 + (tx >> 1)) * 4;
#pragma unroll
    for (int i = 0; i < 4; i++) {
        float s = s_scale[ty * 4 + i];
        float4 o = make_float4(r[i][0] * s, r[i][1] * s, r[i][2] * s, r[i][3] * s);
        *(float4*)(g_featsA + (size_t)(n0 + ty * 4 + i) * FDIM + ppos) = o;
    }
}

// ============================================================
// Kernel 3: one iteration. Warp per node, permuted-row layout:
// lane l owns canonical [8l,8l+8) (channel l>>3) stored at float
// offsets [4l,4l+4) and [128+4l,+4) -> both LDG.128 fully dense.
// 4 neighbors/trip, guard-free, 5 shfls + exp + div per edge.
// launch_bounds(128,8) -> 64 regs -> 8 blocks/SM residency.
// ============================================================
__global__ __launch_bounds__(128, 8) void iterate_kernel(int pass, float* __restrict__ d_final) {
    const float* __restrict__ src = (pass == 1) ? g_featsB : g_featsA;
    float* __restrict__ dst = (pass == 0) ? g_featsB : (pass == 1) ? g_featsA : d_final;

    const int w = threadIdx.x >> 5, lane = threadIdx.x & 31;
    const int n = blockIdx.x * 4 + w;

    const float* xrow = src + (size_t)n * FDIM + lane * 4;
    float4 x0 = *(const float4*)xrow;          // canonical [8l, 8l+4)
    float4 x1 = *(const float4*)(xrow + 128);  // canonical [8l+4, 8l+8)
    float4 a0 = make_float4(0.f, 0.f, 0.f, 0.f);
    float4 a1 = make_float4(0.f, 0.f, 0.f, 0.f);

    const int dp = g_deg[n];                 // padded to multiple of 4
    const int* erow = g_ell + (size_t)n * CAP;

    for (int i = 0; i < dp; i += 4) {
        int col[4];
#pragma unroll
        for (int j = 0; j < 4; j++) col[j] = __ldg(erow + i + j);   // uniform

        float4 y0[4], y1[4];
#pragma unroll
        for (int j = 0; j < 4; j++) {
            const float* yr = src + (size_t)col[j] * FDIM + lane * 4;
            y0[j] = *(const float4*)yr;          // dense 512B across warp
            y1[j] = *(const float4*)(yr + 128);  // dense 512B across warp
        }

        float p[4];
#pragma unroll
        for (int j = 0; j < 4; j++)
            p[j] = x0.x * y0[j].x + x0.y * y0[j].y + x0.z * y0[j].z + x0.w * y0[j].w +
                   x1.x * y1[j].x + x1.y * y1[j].y + x1.z * y1[j].z + x1.w * y1[j].w;
#pragma unroll
        for (int j = 0; j < 4; j++) p[j] += __shfl_xor_sync(0xffffffffu, p[j], 1);
#pragma unroll
        for (int j = 0; j < 4; j++) p[j] += __shfl_xor_sync(0xffffffffu, p[j], 2);
#pragma unroll
        for (int j = 0; j < 4; j++) p[j] += __shfl_xor_sync(0xffffffffu, p[j], 4);
        // |p| <= 1 (unit-norm channel rows): no max-shift needed
        float e[4], t[4];
#pragma unroll
        for (int j = 0; j < 4; j++) e[j] = __expf(p[j]);
#pragma unroll
        for (int j = 0; j < 4; j++) t[j] = e[j] + __shfl_xor_sync(0xffffffffu, e[j], 8);
#pragma unroll
        for (int j = 0; j < 4; j++) t[j] += __shfl_xor_sync(0xffffffffu, t[j], 16);
#pragma unroll
        for (int j = 0; j < 4; j++) {
            float wgt = __fdividef(e[j], t[j]);
            a0.x += wgt * y0[j].x; a0.y += wgt * y0[j].y;
            a0.z += wgt * y0[j].z; a0.w += wgt * y0[j].w;
            a1.x += wgt * y1[j].x; a1.y += wgt * y1[j].y;
            a1.z += wgt * y1[j].z; a1.w += wgt * y1[j].w;
        }
    }

    // self + aggregate, per-channel (8-lane group) L2 norm
    float v[8];
    v[0] = x0.x + a0.x; v[1] = x0.y + a0.y; v[2] = x0.z + a0.z; v[3] = x0.w + a0.w;
    v[4] = x1.x + a1.x; v[5] = x1.y + a1.y; v[6] = x1.z + a1.z; v[7] = x1.w + a1.w;
    float sq = 0.f;
#pragma unroll
    for (int k = 0; k < 8; k++) sq += v[k] * v[k];
    sq += __shfl_xor_sync(0xffffffffu, sq, 1);
    sq += __shfl_xor_sync(0xffffffffu, sq, 2);
    sq += __shfl_xor_sync(0xffffffffu, sq, 4);
    float sc = rsqrtf(fmaxf(sq, 1e-24f));
    if (pass == 2) {
        // canonical layout for d_out: lane's elements are [8l, 8l+8)
        float* drow = dst + (size_t)n * FDIM + lane * 8;
        *(float4*)drow       = make_float4(v[0] * sc, v[1] * sc, v[2] * sc, v[3] * sc);
        *(float4*)(drow + 4) = make_float4(v[4] * sc, v[5] * sc, v[6] * sc, v[7] * sc);
    } else {
        // permuted layout for g_feats
        float* drow = dst + (size_t)n * FDIM + lane * 4;
        *(float4*)drow         = make_float4(v[0] * sc, v[1] * sc, v[2] * sc, v[3] * sc);
        *(float4*)(drow + 128) = make_float4(v[4] * sc, v[5] * sc, v[6] * sc, v[7] * sc);
    }
}

// ============================================================
extern "C" void kernel_launch(void* const* d_in, const int* in_sizes, int n_in,
                              void* d_out, int out_size) {
    const float* features = (const float*)d_in[0];   // [6144, 512]
    const int*   adj      = (const int*)d_in[1];     // [6144, 6144]
    const float* W        = (const float*)d_in[2];   // [4, 512, 64]
    const float* b        = (const float*)d_in[3];   // [4, 1, 64]
    float* out = (float*)d_out;                      // [6144, 256]

    build_ell_kernel<<<NN / 8, 256>>>(adj);
    project_kernel<<<dim3(NN / 64, CHANNELS), 256>>>(features, W, b);
    iterate_kernel<<<NN / 4, 128>>>(0, out);
    iterate_kernel<<<NN / 4, 128>>>(1, out);
    iterate_kernel<<<NN / 4, 128>>>(2, out);
}

// round 13
// speedup vs baseline: 1.6233x; 1.6233x over previous
#include <cuda_runtime.h>
#include <cuda_bf16.h>
#include <cstdint>

#define NN 6144
#define IN_DIM 512
#define CHANNELS 4
#define C_DIM 64
#define FDIM 256          // CHANNELS * C_DIM
#define CAP 128           // max neighbors per row (mean ~31, sd ~5.5)

// -------- scratch (device globals; no allocation allowed) --------
// Rows of g_feats are stored PERMUTED: canonical element e (owner lane
// l = e>>3, sub s = e&7) lives at float offset (s>=4)*128 + l*4 + (s&3).
// Dense per-lane 16B neighbor loads + 8-lane channel groups (5-shfl softmax).
// Row NN is a permanent all-zero row (sentinel target).
__device__ float g_featsA[(size_t)(NN + 1) * FDIM];
__device__ float g_featsB[(size_t)(NN + 1) * FDIM];
__device__ int   g_ell[(size_t)NN * CAP + 64];
__device__ int   g_deg[NN];

#define FMA2(d, a, b, c) \
    asm("fma.rn.f32x2 %0, %1, %2, %3;" : "=l"(d) : "l"(a), "l"(b), "l"(c))
#define PACK2(d, x) \
    asm("mov.b64 %0, {%1, %2};" : "=l"(d) : "f"(x), "f"(x))
#define UNPACK2(lo, hi, s) \
    asm("mov.b64 {%0, %1}, %2;" : "=f"(lo), "=f"(hi) : "l"(s))

// ============================================================
// Kernel 1: dense adj -> ELL (order-preserving, deterministic)
// warp/row, int4 + 4-ballot compaction, sentinel padding to x4.
// ============================================================
__global__ __launch_bounds__(256) void build_ell_kernel(const int* __restrict__ adj) {
    int row = blockIdx.x * 8 + (threadIdx.x >> 5);
    int lane = threadIdx.x & 31;
    const int4* arow = (const int4*)(adj + (size_t)row * NN);
    unsigned lt = (1u << lane) - 1u;
    int total = 0;
    int* erow = g_ell + (size_t)row * CAP;
    for (int it = 0; it < NN / 128; it++) {
        int4 v = arow[it * 32 + lane];
        bool p0 = v.x > 0, p1 = v.y > 0, p2 = v.z > 0, p3 = v.w > 0;
        unsigned b0 = __ballot_sync(0xffffffffu, p0);
        unsigned b1 = __ballot_sync(0xffffffffu, p1);
        unsigned b2 = __ballot_sync(0xffffffffu, p2);
        unsigned b3 = __ballot_sync(0xffffffffu, p3);
        int basec = __popc(b0 & lt) + __popc(b1 & lt) + __popc(b2 & lt) + __popc(b3 & lt);
        int idx0 = it * 128 + lane * 4;
        int pos = total + basec;
        if (p0) { if (pos < CAP) erow[pos] = idx0; pos++; }
        if (p1) { if (pos < CAP) erow[pos] = idx0 + 1; pos++; }
        if (p2) { if (pos < CAP) erow[pos] = idx0 + 2; pos++; }
        if (p3) { if (pos < CAP) erow[pos] = idx0 + 3; }
        total += __popc(b0) + __popc(b1) + __popc(b2) + __popc(b3);
    }
    int tc = total < CAP ? total : CAP;
    int pad = (tc + 3) & ~3;
    if (lane < pad - tc) erow[tc + lane] = NN;   // sentinel -> zero row
    if (lane == 0) g_deg[row] = pad;
}

// ============================================================
// Kernel 2: feats0 = l2norm(features @ W + b) -> permuted layout.
// R5 structure (64x64 tile, 256 threads, 4x4 microtile, BK=16,
// packed f32x2, PACK in-loop) with DOUBLE-BUFFERED smem: prefetch
// chunk k+1 to regs during compute of chunk k, one barrier/chunk.
// Inner 16-step loop is byte-identical to the proven R5 loop.
// ============================================================
__global__ __launch_bounds__(256) void project_kernel(const float* __restrict__ feat,
                                                      const float* __restrict__ W,
                                                      const float* __restrict__ bias) {
    __shared__ float sA[2][16][64];
    __shared__ float sB[2][16][64];
    __shared__ float s_scale[64];

    const int c  = blockIdx.y;
    const int n0 = blockIdx.x * 64;
    const int t  = threadIdx.x;
    const int tx = t & 15, ty = t >> 4;

    unsigned long long acc2[2][4];
#pragma unroll
    for (int i = 0; i < 2; i++)
#pragma unroll
        for (int j = 0; j < 4; j++) acc2[i][j] = 0ull;

    const float* Wc = W + (size_t)c * IN_DIM * C_DIM;
    const int lrow = t >> 2, lseg = t & 3;
    const int ld   = t >> 4, lks  = t & 15;

    // preload chunk 0 into buffer 0
    {
        float4 a = *(const float4*)(feat + (size_t)(n0 + lrow) * IN_DIM + lseg * 4);
        sA[0][lseg * 4 + 0][lrow] = a.x;
        sA[0][lseg * 4 + 1][lrow] = a.y;
        sA[0][lseg * 4 + 2][lrow] = a.z;
        sA[0][lseg * 4 + 3][lrow] = a.w;
        float4 bv = *(const float4*)(Wc + (size_t)ld * C_DIM + lks * 4);
        *(float4*)&sB[0][ld][lks * 4] = bv;
    }
    __syncthreads();

    int cur = 0;
    for (int d0 = 0; d0 < IN_DIM; d0 += 16) {
        // prefetch next chunk into registers (overlaps with compute below)
        float4 an, bn;
        const bool hasNext = (d0 + 16 < IN_DIM);
        if (hasNext) {
            an = *(const float4*)(feat + (size_t)(n0 + lrow) * IN_DIM + d0 + 16 + lseg * 4);
            bn = *(const float4*)(Wc + (size_t)(d0 + 16 + ld) * C_DIM + lks * 4);
        }

        // ---- R5 inner loop, verbatim (reads buffer `cur`) ----
#pragma unroll
        for (int d = 0; d < 16; d++) {
            unsigned long long ap0 = *(const unsigned long long*)&sA[cur][d][ty * 4];
            unsigned long long ap1 = *(const unsigned long long*)&sA[cur][d][ty * 4 + 2];
            float4 bv2 = *(const float4*)&sB[cur][d][tx * 4];
            unsigned long long bp0, bp1, bp2, bp3;
            PACK2(bp0, bv2.x); PACK2(bp1, bv2.y); PACK2(bp2, bv2.z); PACK2(bp3, bv2.w);
            FMA2(acc2[0][0], ap0, bp0, acc2[0][0]);
            FMA2(acc2[0][1], ap0, bp1, acc2[0][1]);
            FMA2(acc2[0][2], ap0, bp2, acc2[0][2]);
            FMA2(acc2[0][3], ap0, bp3, acc2[0][3]);
            FMA2(acc2[1][0], ap1, bp0, acc2[1][0]);
            FMA2(acc2[1][1], ap1, bp1, acc2[1][1]);
            FMA2(acc2[1][2], ap1, bp2, acc2[1][2]);
            FMA2(acc2[1][3], ap1, bp3, acc2[1][3]);
        }

        // store prefetched chunk into the other buffer
        if (hasNext) {
            int nxt = cur ^ 1;
            sA[nxt][lseg * 4 + 0][lrow] = an.x;
            sA[nxt][lseg * 4 + 1][lrow] = an.y;
            sA[nxt][lseg * 4 + 2][lrow] = an.z;
            sA[nxt][lseg * 4 + 3][lrow] = an.w;
            *(float4*)&sB[nxt][ld][lks * 4] = bn;
        }
        __syncthreads();
        cur ^= 1;
    }

    float r[4][4];
#pragma unroll
    for (int i = 0; i < 2; i++)
#pragma unroll
        for (int j = 0; j < 4; j++)
            UNPACK2(r[2 * i][j], r[2 * i + 1][j], acc2[i][j]);

    float4 bb4 = *(const float4*)(bias + c * C_DIM + tx * 4);
    float bb[4] = {bb4.x, bb4.y, bb4.z, bb4.w};
    float ss[4];
#pragma unroll
    for (int i = 0; i < 4; i++) {
        float s = 0.f;
#pragma unroll
        for (int j = 0; j < 4; j++) {
            r[i][j] += bb[j];
            s += r[i][j] * r[i][j];
        }
        ss[i] = s;
    }
#pragma unroll
    for (int off = 1; off < 16; off <<= 1)
#pragma unroll
        for (int i = 0; i < 4; i++) ss[i] += __shfl_xor_sync(0xffffffffu, ss[i], off);
    if (tx == 0) {
#pragma unroll
        for (int i = 0; i < 4; i++) s_scale[ty * 4 + i] = rsqrtf(fmaxf(ss[i], 1e-24f));
    }
    __syncthreads();
    // permuted store position for canonical cols c*64 + tx*4 .. +4:
    // owner lane l = c*8 + (tx>>1), half = tx&1
    const int ppos = (tx & 1) * 128 + (c * 8 + (tx >> 1)) * 4;
#pragma unroll
    for (int i = 0; i < 4; i++) {
        float s = s_scale[ty * 4 + i];
        float4 o = make_float4(r[i][0] * s, r[i][1] * s, r[i][2] * s, r[i][3] * s);
        *(float4*)(g_featsA + (size_t)(n0 + ty * 4 + i) * FDIM + ppos) = o;
    }
}

// ============================================================
// Kernel 3: one iteration. Warp per node, permuted-row layout
// (R11 version verbatim: launch_bounds(128), regs ~72, no spills).
// ============================================================
__global__ __launch_bounds__(128) void iterate_kernel(int pass, float* __restrict__ d_final) {
    const float* __restrict__ src = (pass == 1) ? g_featsB : g_featsA;
    float* __restrict__ dst = (pass == 0) ? g_featsB : (pass == 1) ? g_featsA : d_final;

    const int w = threadIdx.x >> 5, lane = threadIdx.x & 31;
    const int n = blockIdx.x * 4 + w;

    const float* xrow = src + (size_t)n * FDIM + lane * 4;
    float4 x0 = *(const float4*)xrow;          // canonical [8l, 8l+4)
    float4 x1 = *(const float4*)(xrow + 128);  // canonical [8l+4, 8l+8)
    float4 a0 = make_float4(0.f, 0.f, 0.f, 0.f);
    float4 a1 = make_float4(0.f, 0.f, 0.f, 0.f);

    const int dp = g_deg[n];                 // padded to multiple of 4
    const int* erow = g_ell + (size_t)n * CAP;

    for (int i = 0; i < dp; i += 4) {
        int col[4];
#pragma unroll
        for (int j = 0; j < 4; j++) col[j] = __ldg(erow + i + j);   // uniform

        float4 y0[4], y1[4];
#pragma unroll
        for (int j = 0; j < 4; j++) {
            const float* yr = src + (size_t)col[j] * FDIM + lane * 4;
            y0[j] = *(const float4*)yr;          // dense 512B across warp
            y1[j] = *(const float4*)(yr + 128);  // dense 512B across warp
        }

        float p[4];
#pragma unroll
        for (int j = 0; j < 4; j++)
            p[j] = x0.x * y0[j].x + x0.y * y0[j].y + x0.z * y0[j].z + x0.w * y0[j].w +
                   x1.x * y1[j].x + x1.y * y1[j].y + x1.z * y1[j].z + x1.w * y1[j].w;
#pragma unroll
        for (int j = 0; j < 4; j++) p[j] += __shfl_xor_sync(0xffffffffu, p[j], 1);
#pragma unroll
        for (int j = 0; j < 4; j++) p[j] += __shfl_xor_sync(0xffffffffu, p[j], 2);
#pragma unroll
        for (int j = 0; j < 4; j++) p[j] += __shfl_xor_sync(0xffffffffu, p[j], 4);
        // |p| <= 1 (unit-norm channel rows): no max-shift needed
        float e[4], t[4];
#pragma unroll
        for (int j = 0; j < 4; j++) e[j] = __expf(p[j]);
#pragma unroll
        for (int j = 0; j < 4; j++) t[j] = e[j] + __shfl_xor_sync(0xffffffffu, e[j], 8);
#pragma unroll
        for (int j = 0; j < 4; j++) t[j] += __shfl_xor_sync(0xffffffffu, t[j], 16);
#pragma unroll
        for (int j = 0; j < 4; j++) {
            float wgt = __fdividef(e[j], t[j]);
            a0.x += wgt * y0[j].x; a0.y += wgt * y0[j].y;
            a0.z += wgt * y0[j].z; a0.w += wgt * y0[j].w;
            a1.x += wgt * y1[j].x; a1.y += wgt * y1[j].y;
            a1.z += wgt * y1[j].z; a1.w += wgt * y1[j].w;
        }
    }

    // self + aggregate, per-channel (8-lane group) L2 norm
    float v[8];
    v[0] = x0.x + a0.x; v[1] = x0.y + a0.y; v[2] = x0.z + a0.z; v[3] = x0.w + a0.w;
    v[4] = x1.x + a1.x; v[5] = x1.y + a1.y; v[6] = x1.z + a1.z; v[7] = x1.w + a1.w;
    float sq = 0.f;
#pragma unroll
    for (int k = 0; k < 8; k++) sq += v[k] * v[k];
    sq += __shfl_xor_sync(0xffffffffu, sq, 1);
    sq += __shfl_xor_sync(0xffffffffu, sq, 2);
    sq += __shfl_xor_sync(0xffffffffu, sq, 4);
    float sc = rsqrtf(fmaxf(sq, 1e-24f));
    if (pass == 2) {
        // canonical layout for d_out: lane's elements are [8l, 8l+8)
        float* drow = dst + (size_t)n * FDIM + lane * 8;
        *(float4*)drow       = make_float4(v[0] * sc, v[1] * sc, v[2] * sc, v[3] * sc);
        *(float4*)(drow + 4) = make_float4(v[4] * sc, v[5] * sc, v[6] * sc, v[7] * sc);
    } else {
        // permuted layout for g_feats
        float* drow = dst + (size_t)n * FDIM + lane * 4;
        *(float4*)drow         = make_float4(v[0] * sc, v[1] * sc, v[2] * sc, v[3] * sc);
        *(float4*)(drow + 128) = make_float4(v[4] * sc, v[5] * sc, v[6] * sc, v[7] * sc);
    }
}

// ============================================================
extern "C" void kernel_launch(void* const* d_in, const int* in_sizes, int n_in,
                              void* d_out, int out_size) {
    const float* features = (const float*)d_in[0];   // [6144, 512]
    const int*   adj      = (const int*)d_in[1];     // [6144, 6144]
    const float* W        = (const float*)d_in[2];   // [4, 512, 64]
    const float* b        = (const float*)d_in[3];   // [4, 1, 64]
    float* out = (float*)d_out;                      // [6144, 256]

    build_ell_kernel<<<NN / 8, 256>>>(adj);
    project_kernel<<<dim3(NN / 64, CHANNELS), 256>>>(features, W, b);
    iterate_kernel<<<NN / 4, 128>>>(0, out);
    iterate_kernel<<<NN / 4, 128>>>(1, out);
    iterate_kernel<<<NN / 4, 128>>>(2, out);
}